// round 12
// baseline (speedup 1.0000x reference)
#include <cuda_runtime.h>
#include <cuda_fp16.h>
#include <cstdint>

// Flash attention, round 9: fp16 m16n8k16 + ldmatrix, M=32/warp, software
// pipelining. vs round 8 (tensor 62.6%, issue 40%): QK(t+1) MMAs are issued
// BETWEEN exp(t) and PV(t) — they depend only on the already-staged K(t+1),
// so the tensor pipe gets ~256-MMA uninterrupted runs and the MUFU/shuffle
// chain of each tile is hidden behind the next tile's QK GEMM.

static constexpr int S_LEN  = 2048;
static constexpr int D      = 64;
static constexpr int BH     = 64;
static constexpr int BM     = 128;
static constexpr int BN     = 64;
static constexpr int NT     = 128;          // 4 warps
static constexpr int NTILES = S_LEN / BN;   // 32
static constexpr int STR    = 72;           // smem stride in halfs (144B row)
static constexpr int KTILE  = BN * STR;
static constexpr float QS   = 0.1803368801111244f;  // 0.125*log2(e)

__device__ __half g_Kh[(size_t)BH * S_LEN * D];   // [bh][key][dim]
__device__ __half g_Vt[(size_t)BH * S_LEN * D];   // [bh][dim][key]

__device__ __forceinline__ uint32_t h2(float hi, float lo) {
    uint32_t r;
    asm("cvt.rn.f16x2.f32 %0, %1, %2;" : "=r"(r) : "f"(hi), "f"(lo));
    return r;
}
__device__ __forceinline__ float ex2f(float x) {
    float r; asm("ex2.approx.f32 %0, %1;" : "=f"(r) : "f"(x)); return r;
}
__device__ __forceinline__ void cp16(uint32_t dst, const void* src) {
    asm volatile("cp.async.ca.shared.global [%0], [%1], 16;"
                 :: "r"(dst), "l"(src));
}
__device__ __forceinline__ uint32_t smem_u32(const void* p) {
    uint32_t a;
    asm("{ .reg .u64 t; cvta.to.shared.u64 t, %1; cvt.u32.u64 %0, t; }"
        : "=r"(a) : "l"(p));
    return a;
}
__device__ __forceinline__ void ldsm4(uint32_t* r, uint32_t addr) {
    asm volatile("ldmatrix.sync.aligned.m8n8.x4.shared.b16 {%0,%1,%2,%3}, [%4];"
                 : "=r"(r[0]), "=r"(r[1]), "=r"(r[2]), "=r"(r[3])
                 : "r"(addr));
}
__device__ __forceinline__ void mma_f16(float* c, const uint32_t* a,
                                        const uint32_t* b) {
    asm volatile(
        "mma.sync.aligned.m16n8k16.row.col.f32.f16.f16.f32 "
        "{%0,%1,%2,%3}, {%4,%5,%6,%7}, {%8,%9}, {%0,%1,%2,%3};"
        : "+f"(c[0]), "+f"(c[1]), "+f"(c[2]), "+f"(c[3])
        : "r"(a[0]), "r"(a[1]), "r"(a[2]), "r"(a[3]), "r"(b[0]), "r"(b[1]));
}

// ---- merged prepass: K fp32->fp16, V -> fp16 transposed ----
__global__ __launch_bounds__(256)
void conv_kv_kernel(const float* __restrict__ k, const float* __restrict__ v) {
    __shared__ float sv[64][65];
    const int tile = blockIdx.x;
    const int bh   = blockIdx.y;
    const int t    = threadIdx.x;
    const size_t base = ((size_t)bh * S_LEN + tile * 64) * D;

    const float4* ksrc = (const float4*)(k + base);
#pragma unroll
    for (int i = 0; i < 4; i++) {
        int idx = i * 256 + t;
        float4 u = ksrc[idx];
        uint2 o;
        o.x = h2(u.y, u.x);
        o.y = h2(u.w, u.z);
        *(uint2*)&g_Kh[base + idx * 4] = o;
    }

    const float4* vsrc = (const float4*)(v + base);
#pragma unroll
    for (int i = 0; i < 4; i++) {
        int idx = i * 256 + t;
        int r = idx >> 4, c4 = (idx & 15) * 4;
        float4 u = vsrc[idx];
        sv[r][c4] = u.x; sv[r][c4 + 1] = u.y;
        sv[r][c4 + 2] = u.z; sv[r][c4 + 3] = u.w;
    }
    __syncthreads();
#pragma unroll
    for (int i = 0; i < 2; i++) {
        int oidx = i * 256 + t;
        int dim = oidx >> 3, kc = (oidx & 7) * 8;
        uint4 o;
        o.x = h2(sv[kc + 1][dim], sv[kc + 0][dim]);
        o.y = h2(sv[kc + 3][dim], sv[kc + 2][dim]);
        o.z = h2(sv[kc + 5][dim], sv[kc + 4][dim]);
        o.w = h2(sv[kc + 7][dim], sv[kc + 6][dim]);
        *(uint4*)&g_Vt[((size_t)bh * D + dim) * S_LEN + tile * 64 + kc] = o;
    }
}

// QK GEMM for one staged K tile: Sv[2][8][4] = AQ @ K^T
#define QK_GEMM(SV, AQ, KBASE)                                                 \
    do {                                                                       \
        _Pragma("unroll")                                                      \
        for (int m = 0; m < 2; m++)                                            \
            _Pragma("unroll")                                                  \
            for (int nb = 0; nb < 8; nb++)                                     \
                _Pragma("unroll")                                              \
                for (int i = 0; i < 4; i++) (SV)[m][nb][i] = 0.0f;             \
        _Pragma("unroll")                                                      \
        for (int ks = 0; ks < 4; ks++) {                                       \
            _Pragma("unroll")                                                  \
            for (int npb = 0; npb < 4; npb++) {                                \
                uint32_t bb[4];                                                \
                ldsm4(bb, (KBASE) + (uint32_t)(16 * npb * STR + 16 * ks) * 2u);\
                mma_f16((SV)[0][2 * npb],     (AQ)[0][ks], bb);                \
                mma_f16((SV)[0][2 * npb + 1], (AQ)[0][ks], bb + 2);            \
                mma_f16((SV)[1][2 * npb],     (AQ)[1][ks], bb);                \
                mma_f16((SV)[1][2 * npb + 1], (AQ)[1][ks], bb + 2);            \
            }                                                                  \
        }                                                                      \
    } while (0)

// ---- main kernel ----
__global__ __launch_bounds__(NT, 2)
void fa_f16_v9(const float* __restrict__ q, float* __restrict__ out)
{
    __shared__ __align__(16) __half Ks[2][KTILE];
    __shared__ __align__(16) __half Vs[2][KTILE];

    const int t    = threadIdx.x;
    const int lane = t & 31;
    const int warp = t >> 5;
    const int gr   = lane >> 2;
    const int gc   = lane & 3;
    const int bh   = blockIdx.y;
    const int qrow = blockIdx.x * BM + warp * 32;

    const uint32_t ks0 = smem_u32(Ks);
    const uint32_t vs0 = smem_u32(Vs);
    const __half* kg = g_Kh + (size_t)bh * S_LEN * D;
    const __half* vg = g_Vt + (size_t)bh * D * S_LEN;

    const int sr = t >> 3;          // rows sr, sr+16, sr+32, sr+48
    const int sc = (t & 7) * 8;

    const int lr = (lane & 7) | ((lane & 16) >> 1);
    const int lc = lane & 8;
    const uint32_t lmo = (uint32_t)(lr * STR + lc) * 2u;

    // ---- prologue: stage tile 0, then tile 1 in flight ----
#pragma unroll
    for (int i = 0; i < 4; i++) {
        int r = sr + i * 16;
        cp16(ks0 + (uint32_t)(r * STR + sc) * 2u, kg + r * D + sc);
        cp16(vs0 + (uint32_t)(r * STR + sc) * 2u, vg + r * S_LEN + sc);
    }
    asm volatile("cp.async.commit_group;" ::: "memory");

    // Q fragments while tile 0 loads
    uint32_t AQ[2][4][4];
#pragma unroll
    for (int m = 0; m < 2; m++) {
        const float* q0 = q + ((size_t)bh * S_LEN + qrow + 16 * m + gr) * D;
        const float* q1 = q0 + 8 * D;
#pragma unroll
        for (int ks = 0; ks < 4; ks++) {
            int c = 16 * ks + 2 * gc;
            AQ[m][ks][0] = h2(q0[c + 1] * QS, q0[c] * QS);
            AQ[m][ks][1] = h2(q1[c + 1] * QS, q1[c] * QS);
            AQ[m][ks][2] = h2(q0[c + 9] * QS, q0[c + 8] * QS);
            AQ[m][ks][3] = h2(q1[c + 9] * QS, q1[c + 8] * QS);
        }
    }

    float O[2][8][4];
#pragma unroll
    for (int m = 0; m < 2; m++)
#pragma unroll
        for (int nb = 0; nb < 8; nb++)
#pragma unroll
            for (int i = 0; i < 4; i++) O[m][nb][i] = 0.0f;
    float sums[2][2] = {{0.0f, 0.0f}, {0.0f, 0.0f}};

    asm volatile("cp.async.wait_group 0;" ::: "memory");
    __syncthreads();   // tile 0 visible to all warps

    // prefetch tile 1 into stage 1
    {
        const __half* ksrc = kg + 1 * BN * D;
        const __half* vsrc = vg + 1 * BN;
#pragma unroll
        for (int i = 0; i < 4; i++) {
            int r = sr + i * 16;
            cp16(ks0 + (uint32_t)(KTILE + r * STR + sc) * 2u, ksrc + r * D + sc);
            cp16(vs0 + (uint32_t)(KTILE + r * STR + sc) * 2u, vsrc + r * S_LEN + sc);
        }
        asm volatile("cp.async.commit_group;" ::: "memory");
    }

    // QK(0)
    float Sv[2][8][4];
    QK_GEMM(Sv, AQ, ks0 + lmo);

#pragma unroll 1
    for (int tile = 0; tile < NTILES; tile++) {
        // ---- exp(tile): Sv -> packed fp16 P, fp32 row sums ----
        uint32_t h01[2][8], h23[2][8];
#pragma unroll
        for (int m = 0; m < 2; m++)
#pragma unroll
            for (int nb = 0; nb < 8; nb++) {
                float p0 = ex2f(Sv[m][nb][0]);
                float p1 = ex2f(Sv[m][nb][1]);
                float p2 = ex2f(Sv[m][nb][2]);
                float p3 = ex2f(Sv[m][nb][3]);
                sums[m][0] += p0 + p1;
                sums[m][1] += p2 + p3;
                h01[m][nb] = h2(p1, p0);
                h23[m][nb] = h2(p3, p2);
            }

        // ---- make tile+1 visible, then QK(tile+1) fills the exp->PV gap ----
        if (tile + 1 < NTILES) {
            asm volatile("cp.async.wait_group 0;" ::: "memory");
            __syncthreads();
            const uint32_t kB1 =
                ks0 + (uint32_t)(((tile + 1) & 1) * KTILE) * 2u + lmo;
            QK_GEMM(Sv, AQ, kB1);
        }

        // ---- PV(tile): O += P @ V ----
        const uint32_t vB = vs0 + (uint32_t)((tile & 1) * KTILE) * 2u + lmo;
        const int src = 4 * gr + gc;
#pragma unroll
        for (int ks = 0; ks < 4; ks++) {
            uint32_t Ap[2][4];
#pragma unroll
            for (int m = 0; m < 2; m++) {
                Ap[m][0] = __shfl_sync(0xffffffffu, h01[m][2 * ks],     src);
                Ap[m][1] = __shfl_sync(0xffffffffu, h23[m][2 * ks],     src);
                Ap[m][2] = __shfl_sync(0xffffffffu, h01[m][2 * ks + 1], src);
                Ap[m][3] = __shfl_sync(0xffffffffu, h23[m][2 * ks + 1], src);
            }
#pragma unroll
            for (int npb = 0; npb < 4; npb++) {
                uint32_t bb[4];
                ldsm4(bb, vB + (uint32_t)(16 * npb * STR + 16 * ks) * 2u);
                mma_f16(O[0][2 * npb],     Ap[0], bb);
                mma_f16(O[0][2 * npb + 1], Ap[0], bb + 2);
                mma_f16(O[1][2 * npb],     Ap[1], bb);
                mma_f16(O[1][2 * npb + 1], Ap[1], bb + 2);
            }
        }

        // ---- stage tile&1 free now; prefetch tile+2 into it ----
        __syncthreads();
        if (tile + 2 < NTILES) {
            const __half* ksrc = kg + (tile + 2) * BN * D;
            const __half* vsrc = vg + (tile + 2) * BN;
            const uint32_t kd = ks0 + (uint32_t)((tile & 1) * KTILE) * 2u;
            const uint32_t vd = vs0 + (uint32_t)((tile & 1) * KTILE) * 2u;
#pragma unroll
            for (int i = 0; i < 4; i++) {
                int r = sr + i * 16;
                cp16(kd + (uint32_t)(r * STR + sc) * 2u, ksrc + r * D + sc);
                cp16(vd + (uint32_t)(r * STR + sc) * 2u, vsrc + r * S_LEN + sc);
            }
            asm volatile("cp.async.commit_group;" ::: "memory");
        }
    }

    // ---- quad-reduce sums, normalize, store ----
#pragma unroll
    for (int m = 0; m < 2; m++) {
#pragma unroll
        for (int h = 0; h < 2; h++) {
            sums[m][h] += __shfl_xor_sync(0xffffffffu, sums[m][h], 1);
            sums[m][h] += __shfl_xor_sync(0xffffffffu, sums[m][h], 2);
        }
        const float i0 = 1.0f / sums[m][0];
        const float i1 = 1.0f / sums[m][1];
        float* o0 = out + ((size_t)bh * S_LEN + qrow + 16 * m + gr) * D;
        float* o1 = o0 + 8 * D;
#pragma unroll
        for (int nb = 0; nb < 8; nb++) {
            ((float2*)o0)[4 * nb + gc] =
                make_float2(O[m][nb][0] * i0, O[m][nb][1] * i0);
            ((float2*)o1)[4 * nb + gc] =
                make_float2(O[m][nb][2] * i1, O[m][nb][3] * i1);
        }
    }
}

extern "C" void kernel_launch(void* const* d_in, const int* in_sizes, int n_in,
                              void* d_out, int out_size) {
    const float* q = (const float*)d_in[0];
    const float* k = (const float*)d_in[1];
    const float* v = (const float*)d_in[2];
    float* out = (float*)d_out;

    conv_kv_kernel<<<dim3(NTILES, BH), 256>>>(k, v);

    dim3 grid(S_LEN / BM, BH);
    fa_f16_v9<<<grid, NT>>>(q, out);
}

// round 13
// speedup vs baseline: 1.1753x; 1.1753x over previous
#include <cuda_runtime.h>
#include <cuda_fp16.h>
#include <cstdint>

// Flash attention, round 12: fp16 m16n8k16 + ldmatrix, M=32/warp, STREAMED
// softmax. Round-9's coarse pipelining (QK(t+1) before PV(t)) spilled
// (regs=255). Same overlap, register-lean: process the tile in 4 pairs of
// key-blocks — QK(pair j) -> exp(j) -> PV(j) — so only a 16-key slice of S
// is ever live, and pair j+1's QK MMAs (independent) overlap pair j's
// exp/shuffle chain. Peak regs ~155 -> __launch_bounds__(128,3): 3 CTAs/SM.

static constexpr int S_LEN  = 2048;
static constexpr int D      = 64;
static constexpr int BH     = 64;
static constexpr int BM     = 128;
static constexpr int BN     = 64;
static constexpr int NT     = 128;          // 4 warps
static constexpr int NTILES = S_LEN / BN;   // 32
static constexpr int STR    = 72;           // smem stride in halfs (144B row)
static constexpr int KTILE  = BN * STR;
static constexpr float QS   = 0.1803368801111244f;  // 0.125*log2(e)

__device__ __half g_Kh[(size_t)BH * S_LEN * D];   // [bh][key][dim]
__device__ __half g_Vt[(size_t)BH * S_LEN * D];   // [bh][dim][key]

__device__ __forceinline__ uint32_t h2(float hi, float lo) {
    uint32_t r;
    asm("cvt.rn.f16x2.f32 %0, %1, %2;" : "=r"(r) : "f"(hi), "f"(lo));
    return r;
}
__device__ __forceinline__ float ex2f(float x) {
    float r; asm("ex2.approx.f32 %0, %1;" : "=f"(r) : "f"(x)); return r;
}
__device__ __forceinline__ void cp16(uint32_t dst, const void* src) {
    asm volatile("cp.async.ca.shared.global [%0], [%1], 16;"
                 :: "r"(dst), "l"(src));
}
__device__ __forceinline__ uint32_t smem_u32(const void* p) {
    uint32_t a;
    asm("{ .reg .u64 t; cvta.to.shared.u64 t, %1; cvt.u32.u64 %0, t; }"
        : "=r"(a) : "l"(p));
    return a;
}
__device__ __forceinline__ void ldsm4(uint32_t* r, uint32_t addr) {
    asm volatile("ldmatrix.sync.aligned.m8n8.x4.shared.b16 {%0,%1,%2,%3}, [%4];"
                 : "=r"(r[0]), "=r"(r[1]), "=r"(r[2]), "=r"(r[3])
                 : "r"(addr));
}
__device__ __forceinline__ void mma_f16(float* c, const uint32_t* a,
                                        const uint32_t* b) {
    asm volatile(
        "mma.sync.aligned.m16n8k16.row.col.f32.f16.f16.f32 "
        "{%0,%1,%2,%3}, {%4,%5,%6,%7}, {%8,%9}, {%0,%1,%2,%3};"
        : "+f"(c[0]), "+f"(c[1]), "+f"(c[2]), "+f"(c[3])
        : "r"(a[0]), "r"(a[1]), "r"(a[2]), "r"(a[3]), "r"(b[0]), "r"(b[1]));
}

// ---- merged prepass: K fp32->fp16, V -> fp16 transposed ----
__global__ __launch_bounds__(256)
void conv_kv_kernel(const float* __restrict__ k, const float* __restrict__ v) {
    __shared__ float sv[64][65];
    const int tile = blockIdx.x;
    const int bh   = blockIdx.y;
    const int t    = threadIdx.x;
    const size_t base = ((size_t)bh * S_LEN + tile * 64) * D;

    const float4* ksrc = (const float4*)(k + base);
#pragma unroll
    for (int i = 0; i < 4; i++) {
        int idx = i * 256 + t;
        float4 u = ksrc[idx];
        uint2 o;
        o.x = h2(u.y, u.x);
        o.y = h2(u.w, u.z);
        *(uint2*)&g_Kh[base + idx * 4] = o;
    }

    const float4* vsrc = (const float4*)(v + base);
#pragma unroll
    for (int i = 0; i < 4; i++) {
        int idx = i * 256 + t;
        int r = idx >> 4, c4 = (idx & 15) * 4;
        float4 u = vsrc[idx];
        sv[r][c4] = u.x; sv[r][c4 + 1] = u.y;
        sv[r][c4 + 2] = u.z; sv[r][c4 + 3] = u.w;
    }
    __syncthreads();
#pragma unroll
    for (int i = 0; i < 2; i++) {
        int oidx = i * 256 + t;
        int dim = oidx >> 3, kc = (oidx & 7) * 8;
        uint4 o;
        o.x = h2(sv[kc + 1][dim], sv[kc + 0][dim]);
        o.y = h2(sv[kc + 3][dim], sv[kc + 2][dim]);
        o.z = h2(sv[kc + 5][dim], sv[kc + 4][dim]);
        o.w = h2(sv[kc + 7][dim], sv[kc + 6][dim]);
        *(uint4*)&g_Vt[((size_t)bh * D + dim) * S_LEN + tile * 64 + kc] = o;
    }
}

// ---- main kernel ----
__global__ __launch_bounds__(NT, 3)
void fa_f16_v12(const float* __restrict__ q, float* __restrict__ out)
{
    __shared__ __align__(16) __half Ks[2][KTILE];
    __shared__ __align__(16) __half Vs[2][KTILE];

    const int t    = threadIdx.x;
    const int lane = t & 31;
    const int warp = t >> 5;
    const int gr   = lane >> 2;
    const int gc   = lane & 3;
    const int bh   = blockIdx.y;
    const int qrow = blockIdx.x * BM + warp * 32;

    const uint32_t ks0 = smem_u32(Ks);
    const uint32_t vs0 = smem_u32(Vs);
    const __half* kg = g_Kh + (size_t)bh * S_LEN * D;   // [key][dim]
    const __half* vg = g_Vt + (size_t)bh * D * S_LEN;   // [dim][key]

    const int sr = t >> 3;          // rows sr, sr+16, sr+32, sr+48
    const int sc = (t & 7) * 8;

    const int lr = (lane & 7) | ((lane & 16) >> 1);
    const int lc = lane & 8;
    const uint32_t lmo = (uint32_t)(lr * STR + lc) * 2u;

    // ---- prologue: prefetch tile 0 ----
#pragma unroll
    for (int i = 0; i < 4; i++) {
        int r = sr + i * 16;
        cp16(ks0 + (uint32_t)(r * STR + sc) * 2u, kg + r * D + sc);
        cp16(vs0 + (uint32_t)(r * STR + sc) * 2u, vg + r * S_LEN + sc);
    }
    asm volatile("cp.async.commit_group;" ::: "memory");

    // ---- Q fragments for 2 m16 tiles ----
    uint32_t AQ[2][4][4];
#pragma unroll
    for (int m = 0; m < 2; m++) {
        const float* q0 = q + ((size_t)bh * S_LEN + qrow + 16 * m + gr) * D;
        const float* q1 = q0 + 8 * D;
#pragma unroll
        for (int ks = 0; ks < 4; ks++) {
            int c = 16 * ks + 2 * gc;
            AQ[m][ks][0] = h2(q0[c + 1] * QS, q0[c] * QS);
            AQ[m][ks][1] = h2(q1[c + 1] * QS, q1[c] * QS);
            AQ[m][ks][2] = h2(q0[c + 9] * QS, q0[c + 8] * QS);
            AQ[m][ks][3] = h2(q1[c + 9] * QS, q1[c + 8] * QS);
        }
    }

    float O[2][8][4];
#pragma unroll
    for (int m = 0; m < 2; m++)
#pragma unroll
        for (int nb = 0; nb < 8; nb++)
#pragma unroll
            for (int i = 0; i < 4; i++) O[m][nb][i] = 0.0f;
    float sums[2][2] = {{0.0f, 0.0f}, {0.0f, 0.0f}};

    const int shsrc = 4 * gr + gc;

#pragma unroll 1
    for (int tile = 0; tile < NTILES; tile++) {
        __syncthreads();

        if (tile + 1 < NTILES) {
            const __half* ksrc = kg + (tile + 1) * BN * D;
            const __half* vsrc = vg + (tile + 1) * BN;
            const uint32_t kd = ks0 + (uint32_t)(((tile + 1) & 1) * KTILE) * 2u;
            const uint32_t vd = vs0 + (uint32_t)(((tile + 1) & 1) * KTILE) * 2u;
#pragma unroll
            for (int i = 0; i < 4; i++) {
                int r = sr + i * 16;
                cp16(kd + (uint32_t)(r * STR + sc) * 2u, ksrc + r * D + sc);
                cp16(vd + (uint32_t)(r * STR + sc) * 2u, vsrc + r * S_LEN + sc);
            }
        }
        asm volatile("cp.async.commit_group;" ::: "memory");
        asm volatile("cp.async.wait_group 1;" ::: "memory");
        __syncthreads();

        const uint32_t kB = ks0 + (uint32_t)((tile & 1) * KTILE) * 2u + lmo;
        const uint32_t vB = vs0 + (uint32_t)((tile & 1) * KTILE) * 2u + lmo;

        // ---- streamed: per pair j of key-blocks (16 keys) ----
#pragma unroll
        for (int j = 0; j < 4; j++) {
            // QK(j): S slice for keys 16j..16j+15  (4 LDSM, 16 MMA)
            float Sv[2][2][4];
#pragma unroll
            for (int m = 0; m < 2; m++)
#pragma unroll
                for (int nbp = 0; nbp < 2; nbp++)
#pragma unroll
                    for (int i = 0; i < 4; i++) Sv[m][nbp][i] = 0.0f;
#pragma unroll
            for (int ks = 0; ks < 4; ks++) {
                uint32_t bb[4];
                ldsm4(bb, kB + (uint32_t)(16 * j * STR + 16 * ks) * 2u);
                mma_f16(Sv[0][0], AQ[0][ks], bb);
                mma_f16(Sv[0][1], AQ[0][ks], bb + 2);
                mma_f16(Sv[1][0], AQ[1][ks], bb);
                mma_f16(Sv[1][1], AQ[1][ks], bb + 2);
            }

            // exp(j): 16 ex2, pack to half2
            uint32_t h01[2][2], h23[2][2];
#pragma unroll
            for (int m = 0; m < 2; m++)
#pragma unroll
                for (int nbp = 0; nbp < 2; nbp++) {
                    float p0 = ex2f(Sv[m][nbp][0]);
                    float p1 = ex2f(Sv[m][nbp][1]);
                    float p2 = ex2f(Sv[m][nbp][2]);
                    float p3 = ex2f(Sv[m][nbp][3]);
                    sums[m][0] += p0 + p1;
                    sums[m][1] += p2 + p3;
                    h01[m][nbp] = h2(p1, p0);
                    h23[m][nbp] = h2(p3, p2);
                }

            // relayout to A-frag for PV k-step j
            uint32_t Ap[2][4];
#pragma unroll
            for (int m = 0; m < 2; m++) {
                Ap[m][0] = __shfl_sync(0xffffffffu, h01[m][0], shsrc);
                Ap[m][1] = __shfl_sync(0xffffffffu, h23[m][0], shsrc);
                Ap[m][2] = __shfl_sync(0xffffffffu, h01[m][1], shsrc);
                Ap[m][3] = __shfl_sync(0xffffffffu, h23[m][1], shsrc);
            }

            // PV(j): O += P[:,16j:16j+16] @ V[16j:16j+16,:]  (4 LDSM, 16 MMA)
#pragma unroll
            for (int npb = 0; npb < 4; npb++) {
                uint32_t bb[4];
                ldsm4(bb, vB + (uint32_t)(16 * npb * STR + 16 * j) * 2u);
                mma_f16(O[0][2 * npb],     Ap[0], bb);
                mma_f16(O[0][2 * npb + 1], Ap[0], bb + 2);
                mma_f16(O[1][2 * npb],     Ap[1], bb);
                mma_f16(O[1][2 * npb + 1], Ap[1], bb + 2);
            }
        }
    }

    // ---- quad-reduce sums, normalize, store ----
#pragma unroll
    for (int m = 0; m < 2; m++) {
#pragma unroll
        for (int h = 0; h < 2; h++) {
            sums[m][h] += __shfl_xor_sync(0xffffffffu, sums[m][h], 1);
            sums[m][h] += __shfl_xor_sync(0xffffffffu, sums[m][h], 2);
        }
        const float i0 = 1.0f / sums[m][0];
        const float i1 = 1.0f / sums[m][1];
        float* o0 = out + ((size_t)bh * S_LEN + qrow + 16 * m + gr) * D;
        float* o1 = o0 + 8 * D;
#pragma unroll
        for (int nb = 0; nb < 8; nb++) {
            ((float2*)o0)[4 * nb + gc] =
                make_float2(O[m][nb][0] * i0, O[m][nb][1] * i0);
            ((float2*)o1)[4 * nb + gc] =
                make_float2(O[m][nb][2] * i1, O[m][nb][3] * i1);
        }
    }
}

extern "C" void kernel_launch(void* const* d_in, const int* in_sizes, int n_in,
                              void* d_out, int out_size) {
    const float* q = (const float*)d_in[0];
    const float* k = (const float*)d_in[1];
    const float* v = (const float*)d_in[2];
    float* out = (float*)d_out;

    conv_kv_kernel<<<dim3(NTILES, BH), 256>>>(k, v);

    dim3 grid(S_LEN / BM, BH);
    fa_f16_v12<<<grid, NT>>>(q, out);
}

// round 14
// speedup vs baseline: 1.2878x; 1.0957x over previous
#include <cuda_runtime.h>
#include <cuda_fp16.h>
#include <cstdint>

// Flash attention, round 13: round-8 winner (fp16 m16n8k16 + ldmatrix,
// M=32/warp, double-buffered cp.async) with the exp moved to
// ex2.approx.f16x2. Round-8/12 analysis: MUFU (64 ex2.f32/warp/tile,
// rt 8 -> 1024 cyc/SMSP/tile) was co-saturated with tensor (~1059 cyc);
// pipelining couldn't help. f16x2 exp halves MUFU instructions and its
// output IS the packed fp16 P fragment (the old post-exp pack is free).

static constexpr int S_LEN  = 2048;
static constexpr int D      = 64;
static constexpr int BH     = 64;
static constexpr int BM     = 128;
static constexpr int BN     = 64;
static constexpr int NT     = 128;          // 4 warps
static constexpr int NTILES = S_LEN / BN;   // 32
static constexpr int STR    = 72;           // smem stride in halfs (144B row)
static constexpr int KTILE  = BN * STR;
static constexpr float QS   = 0.1803368801111244f;  // 0.125*log2(e)

__device__ __half g_Kh[(size_t)BH * S_LEN * D];   // [bh][key][dim]
__device__ __half g_Vt[(size_t)BH * S_LEN * D];   // [bh][dim][key]

__device__ __forceinline__ uint32_t h2(float hi, float lo) {
    uint32_t r;
    asm("cvt.rn.f16x2.f32 %0, %1, %2;" : "=r"(r) : "f"(hi), "f"(lo));
    return r;
}
__device__ __forceinline__ uint32_t ex2h2(uint32_t s) {
    uint32_t r;
    asm("ex2.approx.f16x2 %0, %1;" : "=r"(r) : "r"(s));
    return r;
}
__device__ __forceinline__ void cp16(uint32_t dst, const void* src) {
    asm volatile("cp.async.ca.shared.global [%0], [%1], 16;"
                 :: "r"(dst), "l"(src));
}
__device__ __forceinline__ uint32_t smem_u32(const void* p) {
    uint32_t a;
    asm("{ .reg .u64 t; cvta.to.shared.u64 t, %1; cvt.u32.u64 %0, t; }"
        : "=r"(a) : "l"(p));
    return a;
}
__device__ __forceinline__ void ldsm4(uint32_t* r, uint32_t addr) {
    asm volatile("ldmatrix.sync.aligned.m8n8.x4.shared.b16 {%0,%1,%2,%3}, [%4];"
                 : "=r"(r[0]), "=r"(r[1]), "=r"(r[2]), "=r"(r[3])
                 : "r"(addr));
}
__device__ __forceinline__ void mma_f16(float* c, const uint32_t* a,
                                        const uint32_t* b) {
    asm volatile(
        "mma.sync.aligned.m16n8k16.row.col.f32.f16.f16.f32 "
        "{%0,%1,%2,%3}, {%4,%5,%6,%7}, {%8,%9}, {%0,%1,%2,%3};"
        : "+f"(c[0]), "+f"(c[1]), "+f"(c[2]), "+f"(c[3])
        : "r"(a[0]), "r"(a[1]), "r"(a[2]), "r"(a[3]), "r"(b[0]), "r"(b[1]));
}

// ---- merged prepass: K fp32->fp16, V -> fp16 transposed ----
__global__ __launch_bounds__(256)
void conv_kv_kernel(const float* __restrict__ k, const float* __restrict__ v) {
    __shared__ float sv[64][65];
    const int tile = blockIdx.x;
    const int bh   = blockIdx.y;
    const int t    = threadIdx.x;
    const size_t base = ((size_t)bh * S_LEN + tile * 64) * D;

    const float4* ksrc = (const float4*)(k + base);
#pragma unroll
    for (int i = 0; i < 4; i++) {
        int idx = i * 256 + t;
        float4 u = ksrc[idx];
        uint2 o;
        o.x = h2(u.y, u.x);
        o.y = h2(u.w, u.z);
        *(uint2*)&g_Kh[base + idx * 4] = o;
    }

    const float4* vsrc = (const float4*)(v + base);
#pragma unroll
    for (int i = 0; i < 4; i++) {
        int idx = i * 256 + t;
        int r = idx >> 4, c4 = (idx & 15) * 4;
        float4 u = vsrc[idx];
        sv[r][c4] = u.x; sv[r][c4 + 1] = u.y;
        sv[r][c4 + 2] = u.z; sv[r][c4 + 3] = u.w;
    }
    __syncthreads();
#pragma unroll
    for (int i = 0; i < 2; i++) {
        int oidx = i * 256 + t;
        int dim = oidx >> 3, kc = (oidx & 7) * 8;
        uint4 o;
        o.x = h2(sv[kc + 1][dim], sv[kc + 0][dim]);
        o.y = h2(sv[kc + 3][dim], sv[kc + 2][dim]);
        o.z = h2(sv[kc + 5][dim], sv[kc + 4][dim]);
        o.w = h2(sv[kc + 7][dim], sv[kc + 6][dim]);
        *(uint4*)&g_Vt[((size_t)bh * D + dim) * S_LEN + tile * 64 + kc] = o;
    }
}

// ---- main kernel ----
__global__ __launch_bounds__(NT, 2)
void fa_f16_v13(const float* __restrict__ q, float* __restrict__ out)
{
    __shared__ __align__(16) __half Ks[2][KTILE];
    __shared__ __align__(16) __half Vs[2][KTILE];

    const int t    = threadIdx.x;
    const int lane = t & 31;
    const int warp = t >> 5;
    const int gr   = lane >> 2;
    const int gc   = lane & 3;
    const int bh   = blockIdx.y;
    const int qrow = blockIdx.x * BM + warp * 32;   // 32 rows per warp

    const uint32_t ks0 = smem_u32(Ks);
    const uint32_t vs0 = smem_u32(Vs);
    const __half* kg = g_Kh + (size_t)bh * S_LEN * D;   // [key][dim]
    const __half* vg = g_Vt + (size_t)bh * D * S_LEN;   // [dim][key]

    const int sr = t >> 3;          // rows sr, sr+16, sr+32, sr+48
    const int sc = (t & 7) * 8;

    const int lr = (lane & 7) | ((lane & 16) >> 1);
    const int lc = lane & 8;
    const uint32_t lmo = (uint32_t)(lr * STR + lc) * 2u;

    // ---- prologue: prefetch tile 0 ----
#pragma unroll
    for (int i = 0; i < 4; i++) {
        int r = sr + i * 16;
        cp16(ks0 + (uint32_t)(r * STR + sc) * 2u, kg + r * D + sc);
        cp16(vs0 + (uint32_t)(r * STR + sc) * 2u, vg + r * S_LEN + sc);
    }
    asm volatile("cp.async.commit_group;" ::: "memory");

    // ---- Q fragments for 2 m16 tiles ----
    uint32_t AQ[2][4][4];
#pragma unroll
    for (int m = 0; m < 2; m++) {
        const float* q0 = q + ((size_t)bh * S_LEN + qrow + 16 * m + gr) * D;
        const float* q1 = q0 + 8 * D;
#pragma unroll
        for (int ks = 0; ks < 4; ks++) {
            int c = 16 * ks + 2 * gc;
            AQ[m][ks][0] = h2(q0[c + 1] * QS, q0[c] * QS);
            AQ[m][ks][1] = h2(q1[c + 1] * QS, q1[c] * QS);
            AQ[m][ks][2] = h2(q0[c + 9] * QS, q0[c + 8] * QS);
            AQ[m][ks][3] = h2(q1[c + 9] * QS, q1[c + 8] * QS);
        }
    }

    float O[2][8][4];
#pragma unroll
    for (int m = 0; m < 2; m++)
#pragma unroll
        for (int nb = 0; nb < 8; nb++)
#pragma unroll
            for (int i = 0; i < 4; i++) O[m][nb][i] = 0.0f;
    float sums[2][2] = {{0.0f, 0.0f}, {0.0f, 0.0f}};

#pragma unroll 1
    for (int tile = 0; tile < NTILES; tile++) {
        __syncthreads();

        if (tile + 1 < NTILES) {
            const __half* ksrc = kg + (tile + 1) * BN * D;
            const __half* vsrc = vg + (tile + 1) * BN;
            const uint32_t kd = ks0 + (uint32_t)(((tile + 1) & 1) * KTILE) * 2u;
            const uint32_t vd = vs0 + (uint32_t)(((tile + 1) & 1) * KTILE) * 2u;
#pragma unroll
            for (int i = 0; i < 4; i++) {
                int r = sr + i * 16;
                cp16(kd + (uint32_t)(r * STR + sc) * 2u, ksrc + r * D + sc);
                cp16(vd + (uint32_t)(r * STR + sc) * 2u, vsrc + r * S_LEN + sc);
            }
        }
        asm volatile("cp.async.commit_group;" ::: "memory");
        asm volatile("cp.async.wait_group 1;" ::: "memory");
        __syncthreads();

        const uint32_t kB = ks0 + (uint32_t)((tile & 1) * KTILE) * 2u + lmo;
        const uint32_t vB = vs0 + (uint32_t)((tile & 1) * KTILE) * 2u + lmo;

        // ---- S = Q @ K^T : 16 LDSM feed 64 MMAs ----
        float Sv[2][8][4];
#pragma unroll
        for (int m = 0; m < 2; m++)
#pragma unroll
            for (int nb = 0; nb < 8; nb++)
#pragma unroll
                for (int i = 0; i < 4; i++) Sv[m][nb][i] = 0.0f;
#pragma unroll
        for (int ks = 0; ks < 4; ks++) {
#pragma unroll
            for (int npb = 0; npb < 4; npb++) {
                uint32_t bb[4];
                ldsm4(bb, kB + (uint32_t)(16 * npb * STR + 16 * ks) * 2u);
                mma_f16(Sv[0][2 * npb],     AQ[0][ks], bb);
                mma_f16(Sv[0][2 * npb + 1], AQ[0][ks], bb + 2);
                mma_f16(Sv[1][2 * npb],     AQ[1][ks], bb);
                mma_f16(Sv[1][2 * npb + 1], AQ[1][ks], bb + 2);
            }
        }

        // ---- p = 2^s via ex2.approx.f16x2 (half the MUFU ops);
        //      output is already the packed fp16 P fragment ----
        uint32_t h01[2][8], h23[2][8];
#pragma unroll
        for (int m = 0; m < 2; m++)
#pragma unroll
            for (int nb = 0; nb < 8; nb++) {
                uint32_t s01 = h2(Sv[m][nb][1], Sv[m][nb][0]);
                uint32_t s23 = h2(Sv[m][nb][3], Sv[m][nb][2]);
                uint32_t p01 = ex2h2(s01);
                uint32_t p23 = ex2h2(s23);
                h01[m][nb] = p01;
                h23[m][nb] = p23;
                float2 f01 = __half22float2(*(const __half2*)&p01);
                float2 f23 = __half22float2(*(const __half2*)&p23);
                sums[m][0] += f01.x + f01.y;
                sums[m][1] += f23.x + f23.y;
            }

        // ---- O += P @ V : 16 LDSM feed 64 MMAs ----
        const int src = 4 * gr + gc;
#pragma unroll
        for (int ks = 0; ks < 4; ks++) {
            uint32_t Ap[2][4];
#pragma unroll
            for (int m = 0; m < 2; m++) {
                Ap[m][0] = __shfl_sync(0xffffffffu, h01[m][2 * ks],     src);
                Ap[m][1] = __shfl_sync(0xffffffffu, h23[m][2 * ks],     src);
                Ap[m][2] = __shfl_sync(0xffffffffu, h01[m][2 * ks + 1], src);
                Ap[m][3] = __shfl_sync(0xffffffffu, h23[m][2 * ks + 1], src);
            }
#pragma unroll
            for (int npb = 0; npb < 4; npb++) {
                uint32_t bb[4];
                ldsm4(bb, vB + (uint32_t)(16 * npb * STR + 16 * ks) * 2u);
                mma_f16(O[0][2 * npb],     Ap[0], bb);
                mma_f16(O[0][2 * npb + 1], Ap[0], bb + 2);
                mma_f16(O[1][2 * npb],     Ap[1], bb);
                mma_f16(O[1][2 * npb + 1], Ap[1], bb + 2);
            }
        }
    }

    // ---- quad-reduce sums, normalize, store ----
#pragma unroll
    for (int m = 0; m < 2; m++) {
#pragma unroll
        for (int h = 0; h < 2; h++) {
            sums[m][h] += __shfl_xor_sync(0xffffffffu, sums[m][h], 1);
            sums[m][h] += __shfl_xor_sync(0xffffffffu, sums[m][h], 2);
        }
        const float i0 = 1.0f / sums[m][0];
        const float i1 = 1.0f / sums[m][1];
        float* o0 = out + ((size_t)bh * S_LEN + qrow + 16 * m + gr) * D;
        float* o1 = o0 + 8 * D;
#pragma unroll
        for (int nb = 0; nb < 8; nb++) {
            ((float2*)o0)[4 * nb + gc] =
                make_float2(O[m][nb][0] * i0, O[m][nb][1] * i0);
            ((float2*)o1)[4 * nb + gc] =
                make_float2(O[m][nb][2] * i1, O[m][nb][3] * i1);
        }
    }
}

extern "C" void kernel_launch(void* const* d_in, const int* in_sizes, int n_in,
                              void* d_out, int out_size) {
    const float* q = (const float*)d_in[0];
    const float* k = (const float*)d_in[1];
    const float* v = (const float*)d_in[2];
    float* out = (float*)d_out;

    conv_kv_kernel<<<dim3(NTILES, BH), 256>>>(k, v);

    dim3 grid(S_LEN / BM, BH);
    fa_f16_v13<<<grid, NT>>>(q, out);
}